// round 14
// baseline (speedup 1.0000x reference)
#include <cuda_runtime.h>
#include <cuda_fp16.h>
#include <math.h>
#include <stdint.h>

#define NB      8
#define LSEQ    4096
#define DMODEL  1024
#define TOPK    16
#define NROWS   (NB * DMODEL)          // 8192
#define MTOT    (NB * LSEQ)            // 32768

// ---------------------------------------------------------------------------
// Scratch (device globals; no runtime allocation allowed)
// ---------------------------------------------------------------------------
__device__ float  g_qT[(size_t)NROWS * LSEQ];   // [b*1024 + hd][l] fp32
__device__ float  g_kT[(size_t)NROWS * LSEQ];
__device__ float  g_vT[(size_t)NROWS * LSEQ];
__device__ __half g_a_hi[(size_t)MTOT * DMODEL];   // agg, batched [(b*1024+hd)*4096+l]
__device__ __half g_wt_hi[4 * DMODEL * DMODEL];    // W^T, [n,k], 4 matrices
__device__ __half g_wt_lo[4 * DMODEL * DMODEL];

extern __shared__ char smem_raw[];

// ---------------------------------------------------------------------------
// PTX helpers (baseline sm_80+: cp.async / ldmatrix / mma)
// ---------------------------------------------------------------------------
__device__ __forceinline__ uint32_t smem_u32(const void* p) {
    uint32_t a;
    asm("{ .reg .u64 t; cvta.to.shared.u64 t, %1; cvt.u32.u64 %0, t; }" : "=r"(a) : "l"(p));
    return a;
}
__device__ __forceinline__ void cpa16(uint32_t d, const void* g) {
    asm volatile("cp.async.cg.shared.global [%0], [%1], 16;" :: "r"(d), "l"(g));
}
#define CPA_COMMIT() asm volatile("cp.async.commit_group;" ::: "memory")
#define CPA_WAIT(n)  asm volatile("cp.async.wait_group %0;" :: "n"(n) : "memory")

#define LDSM4(r0, r1, r2, r3, a) \
    asm volatile("ldmatrix.sync.aligned.m8n8.x4.shared.b16 {%0,%1,%2,%3}, [%4];" \
        : "=r"(r0), "=r"(r1), "=r"(r2), "=r"(r3) : "r"(a))

#define LDSM4T(r0, r1, r2, r3, a) \
    asm volatile("ldmatrix.sync.aligned.m8n8.x4.trans.shared.b16 {%0,%1,%2,%3}, [%4];" \
        : "=r"(r0), "=r"(r1), "=r"(r2), "=r"(r3) : "r"(a))

// fp32-accumulator HMMA
#define MMA16816(d, a, b) \
    asm volatile("mma.sync.aligned.m16n8k16.row.col.f32.f16.f16.f32 " \
        "{%0,%1,%2,%3}, {%4,%5,%6,%7}, {%8,%9}, {%0,%1,%2,%3};" \
        : "+f"((d)[0]), "+f"((d)[1]), "+f"((d)[2]), "+f"((d)[3]) \
        : "r"((a)[0]), "r"((a)[1]), "r"((a)[2]), "r"((a)[3]), "r"((b)[0]), "r"((b)[1]))

// fp16-accumulator HMMA (residual passes; sums stay ~1e-4 so fp16 acc is exact enough)
#define MMA16816H(d, a, b) \
    asm volatile("mma.sync.aligned.m16n8k16.row.col.f16.f16.f16.f16 " \
        "{%0,%1}, {%2,%3,%4,%5}, {%6,%7}, {%0,%1};" \
        : "+r"((d)[0]), "+r"((d)[1]) \
        : "r"((a)[0]), "r"((a)[1]), "r"((a)[2]), "r"((a)[3]), "r"((b)[0]), "r"((b)[1]))

__device__ __forceinline__ uint32_t halves2u32(__half a, __half b) {
    __half2 h = __halves2half2(a, b);
    return *(uint32_t*)&h;
}
__device__ __forceinline__ float2 cmul(float2 a, float2 b) {
    return make_float2(a.x * b.x - a.y * b.y, a.x * b.y + a.y * b.x);
}

// ---------------------------------------------------------------------------
// Batched W [k,n] -> W^T [n,k] hi/lo split (blockIdx.z selects matrix)
// ---------------------------------------------------------------------------
__global__ void __launch_bounds__(256) wsplit_kernel(
    const float* __restrict__ W0, const float* __restrict__ W1,
    const float* __restrict__ W2, const float* __restrict__ W3,
    __half* __restrict__ Thi, __half* __restrict__ Tlo)
{
    const float* W = (blockIdx.z == 0) ? W0 : (blockIdx.z == 1) ? W1
                   : (blockIdx.z == 2) ? W2 : W3;
    __half* hi = Thi + (size_t)blockIdx.z * DMODEL * DMODEL;
    __half* lo = Tlo + (size_t)blockIdx.z * DMODEL * DMODEL;

    __shared__ float t[32][33];
    const int bx = blockIdx.x * 32;
    const int by = blockIdx.y * 32;
    const int tx = threadIdx.x & 31;
    const int ty = threadIdx.x >> 5;
#pragma unroll
    for (int j = 0; j < 4; j++)
        t[ty + j * 8][tx] = W[(size_t)(by + ty + j * 8) * DMODEL + bx + tx];
    __syncthreads();
#pragma unroll
    for (int j = 0; j < 4; j++) {
        const float v = t[tx][ty + j * 8];
        const __half h = __float2half_rn(v);
        const size_t o = (size_t)(bx + ty + j * 8) * DMODEL + by + tx;
        hi[o] = h;
        lo[o] = __float2half_rn(v - __half2float(h));
    }
}

// ---------------------------------------------------------------------------
// Split-fp16 HMMA GEMM, K-slab 32, hi/lo packed in 128B rows.
// Main pass Ah*Bh in f32 acc; residual pass(es) in f16 acc (MMA16816H).
// PASSES=3: + Ah*Bl + Al*Bh (resid) ; PASSES=2: + Ah*Bl (resid)
// MODE 0: A fp32 row-major, split in-kernel; C batched-transposed fp32.
// MODE 1: A fp16 hi batched [(b*1024+k)*4096+l], ldmatrix.trans; C row-major.
// ---------------------------------------------------------------------------
#define SA    0
#define SB    16384
#define STAGE 32768
#define GEMM_SMEM 67584
#define EPS 132

__device__ __forceinline__ int swz(int r, int cb) {     // 128B rows
    return r * 128 + (cb ^ ((r & 7) << 4));
}
__device__ __forceinline__ int swz256(int r, int cb) {  // 256B rows (MODE1 A)
    return r * 256 + (cb ^ ((r & 7) << 4));
}

template<int MODE, int PASSES>
__global__ void __launch_bounds__(256, 1) hgemm_kernel(
    const void* __restrict__ Ain,
    const __half* __restrict__ Bhi, const __half* __restrict__ Blo,
    const float* __restrict__ bias, float* __restrict__ C)
{
    char* smem = smem_raw;
    const int tid  = threadIdx.x;
    const int wid  = tid >> 5;
    const int lane = tid & 31;
    const int n0 = blockIdx.x * 128;
    const int m0 = blockIdx.y * 128;
    const int warp_m = wid & 1;
    const int warp_n = wid >> 1;
    const int bb = m0 >> 12;
    const int l0 = m0 & (LSEQ - 1);
    const uint32_t sbase = smem_u32(smem);

    const float*  Af = (const float*)Ain;    // MODE 0
    const __half* Ah = (const __half*)Ain;   // MODE 1

    float acc[4][4][4];
    uint32_t accR[4][4][2];
#pragma unroll
    for (int mi = 0; mi < 4; mi++)
#pragma unroll
        for (int ni = 0; ni < 4; ni++) {
#pragma unroll
            for (int j = 0; j < 4; j++) acc[mi][ni][j] = 0.0f;
            accR[mi][ni][0] = 0u;
            accR[mi][ni][1] = 0u;
        }

    float4 ar[4];   // MODE 0 prefetch

    auto loadStage = [&](int st, int kt) {
        const uint32_t sb = sbase + st * STAGE;
#pragma unroll
        for (int i = 0; i < 4; i++) {
            const int idx = tid + i * 256;
            const int rr = idx >> 3, ch = idx & 7;
            const bool ishi = (ch < 4);
            const int c4 = ch & 3;
            const __half* src = (ishi ? Bhi : Blo) + (size_t)(n0 + rr) * DMODEL + kt + c4 * 8;
            cpa16(sb + SB + swz(rr, (ishi ? 0 : 64) + c4 * 16), src);
        }
        if (MODE == 1) {
#pragma unroll
            for (int i = 0; i < 2; i++) {
                const int idx = tid + i * 256;
                const int rr = idx >> 4;
                const int ch = idx & 15;
                const __half* src = Ah + ((size_t)(bb * DMODEL + kt + rr)) * LSEQ + l0 + ch * 8;
                cpa16(sb + SA + swz256(rr, ch * 16), src);
            }
        }
        CPA_COMMIT();
    };

    auto ldgA = [&](int kt) {
        if (MODE == 0) {
#pragma unroll
            for (int j = 0; j < 4; j++) {
                const int c = tid + j * 256;
                const int rr = c >> 3, c4 = c & 7;
                ar[j] = *(const float4*)(Af + (size_t)(m0 + rr) * DMODEL + kt + c4 * 4);
            }
        }
    };

    auto stsA = [&](int st) {
        if (MODE == 0) {
            char* buf = smem + st * STAGE + SA;
#pragma unroll
            for (int j = 0; j < 4; j++) {
                const int c = tid + j * 256;
                const int rr = c >> 3, c4 = c & 7;
                const float4 v = ar[j];
                const __half h0 = __float2half_rn(v.x);
                const __half h1 = __float2half_rn(v.y);
                const __half h2 = __float2half_rn(v.z);
                const __half h3 = __float2half_rn(v.w);
                const int xo = ((rr & 7) << 4);
                const int half8 = (c4 & 1) * 8;
                uint2 hh;
                hh.x = halves2u32(h0, h1);
                hh.y = halves2u32(h2, h3);
                *(uint2*)(buf + rr * 128 + (((c4 >> 1) * 16) ^ xo) + half8) = hh;
                if (PASSES == 3) {
                    uint2 ll;
                    ll.x = halves2u32(__float2half_rn(v.x - __half2float(h0)),
                                      __float2half_rn(v.y - __half2float(h1)));
                    ll.y = halves2u32(__float2half_rn(v.z - __half2float(h2)),
                                      __float2half_rn(v.w - __half2float(h3)));
                    *(uint2*)(buf + rr * 128 + ((64 + (c4 >> 1) * 16) ^ xo) + half8) = ll;
                }
            }
        }
    };

    loadStage(0, 0);
    ldgA(0);
    stsA(0);

    for (int s = 0; s < 32; s++) {
        if (s < 31) { loadStage((s + 1) & 1, (s + 1) * 32); ldgA((s + 1) * 32); }
        if (s < 31) { CPA_WAIT(1); } else { CPA_WAIT(0); }
        __syncthreads();

        const uint32_t sb = sbase + (s & 1) * STAGE;
#pragma unroll
        for (int kk = 0; kk < 2; kk++) {
            uint32_t ahi[4][4], alo[4][4], bhi[4][2], blo[4][2];
            if (MODE == 0) {
                const int arr = warp_m * 64 + (lane & 15);
                const int acb = kk * 32 + (lane >> 4) * 16;
#pragma unroll
                for (int mi = 0; mi < 4; mi++) {
                    const int r = arr + mi * 16;
                    LDSM4(ahi[mi][0], ahi[mi][1], ahi[mi][2], ahi[mi][3], sb + SA + swz(r, acb));
                    if (PASSES == 3)
                        LDSM4(alo[mi][0], alo[mi][1], alo[mi][2], alo[mi][3],
                              sb + SA + swz(r, 64 + acb));
                }
            } else {
                const int krow = kk * 16 + (lane & 7) + ((lane >> 4) & 1) * 8;
                const int mcb0 = (warp_m * 64) * 2 + ((lane >> 3) & 1) * 16;
#pragma unroll
                for (int mi = 0; mi < 4; mi++)
                    LDSM4T(ahi[mi][0], ahi[mi][1], ahi[mi][2], ahi[mi][3],
                           sb + SA + swz256(krow, mcb0 + mi * 32));
            }
            const int br = warp_n * 32 + ((lane >> 4) << 3) + (lane & 7);
            const int bcb = kk * 32 + ((lane >> 3) & 1) * 16;
#pragma unroll
            for (int ni2 = 0; ni2 < 2; ni2++) {
                const int r = br + ni2 * 16;
                LDSM4(bhi[ni2 * 2][0], bhi[ni2 * 2][1], bhi[ni2 * 2 + 1][0], bhi[ni2 * 2 + 1][1],
                      sb + SB + swz(r, bcb));
                LDSM4(blo[ni2 * 2][0], blo[ni2 * 2][1], blo[ni2 * 2 + 1][0], blo[ni2 * 2 + 1][1],
                      sb + SB + swz(r, 64 + bcb));
            }
            // main pass: f32 accumulator
#pragma unroll
            for (int mi = 0; mi < 4; mi++)
#pragma unroll
                for (int ni = 0; ni < 4; ni++)
                    MMA16816(acc[mi][ni], ahi[mi], bhi[ni]);
            // residual passes: f16 accumulator (values stay tiny; exact enough)
#pragma unroll
            for (int mi = 0; mi < 4; mi++)
#pragma unroll
                for (int ni = 0; ni < 4; ni++)
                    MMA16816H(accR[mi][ni], ahi[mi], blo[ni]);
            if (PASSES == 3) {
#pragma unroll
                for (int mi = 0; mi < 4; mi++)
#pragma unroll
                    for (int ni = 0; ni < 4; ni++)
                        MMA16816H(accR[mi][ni], alo[mi], bhi[ni]);
            }
        }
        if (s < 31) stsA((s + 1) & 1);
        __syncthreads();
    }

    // ---- epilogue via smem for coalesced stores ----
    float* ep = (float*)smem;
#pragma unroll
    for (int mi = 0; mi < 4; mi++) {
        const int r0 = warp_m * 64 + mi * 16 + (lane >> 2);
#pragma unroll
        for (int ni = 0; ni < 4; ni++) {
            const int c = warp_n * 32 + ni * 8 + 2 * (lane & 3);
            const float b0 = bias[n0 + c];
            const float b1 = bias[n0 + c + 1];
            const __half2 rA = *(__half2*)&accR[mi][ni][0];   // {c0, c1}
            const __half2 rB = *(__half2*)&accR[mi][ni][1];   // {c2, c3}
            const float v0 = acc[mi][ni][0] + __low2float(rA)  + b0;
            const float v1 = acc[mi][ni][1] + __high2float(rA) + b1;
            const float v2 = acc[mi][ni][2] + __low2float(rB)  + b0;
            const float v3 = acc[mi][ni][3] + __high2float(rB) + b1;
            if (MODE == 0) {
                ep[(c    ) * EPS + r0    ] = v0;
                ep[(c + 1) * EPS + r0    ] = v1;
                ep[(c    ) * EPS + r0 + 8] = v2;
                ep[(c + 1) * EPS + r0 + 8] = v3;
            } else {
                ep[(r0    ) * EPS + c    ] = v0;
                ep[(r0    ) * EPS + c + 1] = v1;
                ep[(r0 + 8) * EPS + c    ] = v2;
                ep[(r0 + 8) * EPS + c + 1] = v3;
            }
        }
    }
    __syncthreads();
#pragma unroll
    for (int j = 0; j < 16; j++) {
        const int row = j * 8 + wid;
        const float4 v = *(const float4*)(ep + row * EPS + lane * 4);
        if (MODE == 0)
            *(float4*)(C + ((size_t)(bb * DMODEL + n0 + row)) * LSEQ + l0 + lane * 4) = v;
        else
            *(float4*)(C + (size_t)(m0 + row) * DMODEL + n0 + lane * 4) = v;
    }
}

// ---------------------------------------------------------------------------
// Fused correlation kernel (unchanged from R13 pass: 64KB, vbuf aliases Az)
// ---------------------------------------------------------------------------
#define CORR_SMEM_BYTES (2 * LSEQ * 8 + 64 * 4)

__device__ __forceinline__ void fft4096(float2* buf0, float2* buf1, int tid)
{
    const float C707 = 0.70710678118654752f;
    float2* src = buf0;
    float2* dst = buf1;
    int m = 1;
    for (int st = 0; st < 4; st++) {
        __syncthreads();
        const int k  = tid & (m - 1);
        const int Jm = tid - k;
        const float2 x0 = src[tid];
        const float2 x1 = src[tid + 512];
        const float2 x2 = src[tid + 1024];
        const float2 x3 = src[tid + 1536];
        const float2 x4 = src[tid + 2048];
        const float2 x5 = src[tid + 2560];
        const float2 x6 = src[tid + 3072];
        const float2 x7 = src[tid + 3584];
        const float a0x = x0.x + x4.x, a0y = x0.y + x4.y;
        const float a1x = x0.x - x4.x, a1y = x0.y - x4.y;
        const float b0x = x2.x + x6.x, b0y = x2.y + x6.y;
        const float b1x = x2.x - x6.x, b1y = x2.y - x6.y;
        const float E0x = a0x + b0x, E0y = a0y + b0y;
        const float E1x = a1x + b1y, E1y = a1y - b1x;
        const float E2x = a0x - b0x, E2y = a0y - b0y;
        const float E3x = a1x - b1y, E3y = a1y + b1x;
        const float c0x = x1.x + x5.x, c0y = x1.y + x5.y;
        const float c1x = x1.x - x5.x, c1y = x1.y - x5.y;
        const float d0x = x3.x + x7.x, d0y = x3.y + x7.y;
        const float d1x = x3.x - x7.x, d1y = x3.y - x7.y;
        const float O0x = c0x + d0x, O0y = c0y + d0y;
        const float O1x = c1x + d1y, O1y = c1y - d1x;
        const float O2x = c0x - d0x, O2y = c0y - d0y;
        const float O3x = c1x - d1y, O3y = c1y + d1x;
        const float t1x = C707 * (O1x + O1y), t1y = C707 * (O1y - O1x);
        const float t2x = O2y,               t2y = -O2x;
        const float t3x = C707 * (O3y - O3x), t3y = -C707 * (O3x + O3y);
        const float2 y0 = make_float2(E0x + O0x, E0y + O0y);
        const float2 y4 = make_float2(E0x - O0x, E0y - O0y);
        const float2 y1 = make_float2(E1x + t1x, E1y + t1y);
        const float2 y5 = make_float2(E1x - t1x, E1y - t1y);
        const float2 y2 = make_float2(E2x + t2x, E2y + t2y);
        const float2 y6 = make_float2(E2x - t2x, E2y - t2y);
        const float2 y3 = make_float2(E3x + t3x, E3y + t3y);
        const float2 y7 = make_float2(E3x - t3x, E3y - t3y);
        const float ang = -1.5339807878856412e-3f * (float)Jm;
        float s1, cc1;
        __sincosf(ang, &s1, &cc1);
        const float2 w1 = make_float2(cc1, s1);
        const float2 w2 = cmul(w1, w1);
        const float2 w3 = cmul(w2, w1);
        const float2 w4 = cmul(w2, w2);
        const float2 w5 = cmul(w3, w2);
        const float2 w6 = cmul(w3, w3);
        const float2 w7 = cmul(w4, w3);
        const int base = 8 * Jm + k;
        dst[base]         = y0;
        dst[base + m]     = cmul(y1, w1);
        dst[base + 2 * m] = cmul(y2, w2);
        dst[base + 3 * m] = cmul(y3, w3);
        dst[base + 4 * m] = cmul(y4, w4);
        dst[base + 5 * m] = cmul(y5, w5);
        dst[base + 6 * m] = cmul(y6, w6);
        dst[base + 7 * m] = cmul(y7, w7);
        float2* t = src; src = dst; dst = t;
        m <<= 3;
    }
    __syncthreads();
}

__global__ void __launch_bounds__(512, 2) corr_kernel(
    const float* __restrict__ qT, const float* __restrict__ kT,
    const float* __restrict__ vT, __half* __restrict__ aHi)
{
    float* smem = (float*)smem_raw;
    float2* Az   = (float2*)smem;
    float2* Bz   = Az + LSEQ;
    float*  tail = (float*)(Bz + LSEQ);
    float*  rval = tail;
    int*    ridx = (int*)(rval + 16);
    float*  wts  = (float*)(ridx + 16);
    int*    dly  = (int*)(wts + 16);
    float*  vbuf = (float*)Az;

    const int tid = threadIdx.x;
    const size_t row = blockIdx.x;
    const float* qp = qT + row * LSEQ;
    const float* kp = kT + row * LSEQ;
    const float* vp = vT + row * LSEQ;

#pragma unroll
    for (int i4 = tid; i4 < LSEQ / 4; i4 += 512) {
        const float4 q4 = ((const float4*)qp)[i4];
        const float4 k4 = ((const float4*)kp)[i4];
        Az[i4 * 4 + 0] = make_float2(q4.x, k4.x);
        Az[i4 * 4 + 1] = make_float2(q4.y, k4.y);
        Az[i4 * 4 + 2] = make_float2(q4.z, k4.z);
        Az[i4 * 4 + 3] = make_float2(q4.w, k4.w);
    }

    fft4096(Az, Bz, tid);

    for (int f = tid; f < LSEQ; f += 512) {
        const float2 zf = Az[f];
        const float2 zc = Az[(LSEQ - f) & (LSEQ - 1)];
        const float qx = 0.5f * (zf.x + zc.x);
        const float qy = 0.5f * (zf.y - zc.y);
        const float dx = 0.5f * (zf.x - zc.x);
        const float dy = 0.5f * (zf.y + zc.y);
        const float kx = dy;
        const float ky = -dx;
        const float sx = qx * kx + qy * ky;
        const float sy = qy * kx - qx * ky;
        Bz[f] = make_float2(sx, -sy);
    }

    fft4096(Bz, Az, tid);

    float cv[8];
#pragma unroll
    for (int c = 0; c < 8; c++) cv[c] = Bz[tid + 512 * c].x;

#pragma unroll
    for (int i4 = tid; i4 < LSEQ / 4; i4 += 512)
        *(float4*)(vbuf + i4 * 4) = ((const float4*)vp)[i4];

    const int lane = tid & 31;
    const int wrp  = tid >> 5;
    for (int it = 0; it < TOPK; it++) {
        float best = cv[0];
        int   bc   = 0;
#pragma unroll
        for (int c = 1; c < 8; c++)
            if (cv[c] > best) { best = cv[c]; bc = c; }
        int bi = tid + 512 * bc;
#pragma unroll
        for (int off = 16; off; off >>= 1) {
            const float ov = __shfl_down_sync(0xffffffffu, best, off);
            const int   oi = __shfl_down_sync(0xffffffffu, bi, off);
            if (ov > best || (ov == best && oi < bi)) { best = ov; bi = oi; }
        }
        if (lane == 0) { rval[wrp] = best; ridx[wrp] = bi; }
        __syncthreads();
        if (tid < 32) {
            float v = (lane < 16) ? rval[lane] : -INFINITY;
            int   i = (lane < 16) ? ridx[lane] : LSEQ;
#pragma unroll
            for (int off = 8; off; off >>= 1) {
                const float ov = __shfl_down_sync(0xffffffffu, v, off);
                const int   oi = __shfl_down_sync(0xffffffffu, i, off);
                if (ov > v || (ov == v && oi < i)) { v = ov; i = oi; }
            }
            if (lane == 0) { wts[it] = v * (1.0f / (float)LSEQ); dly[it] = i; }
        }
        __syncthreads();
        const int gi = dly[it];
        if (tid == (gi & 511)) cv[gi >> 9] = -INFINITY;
    }

    if (tid == 0) {
        float mx = wts[0];
        for (int i = 1; i < TOPK; i++) mx = fmaxf(mx, wts[i]);
        float s = 0.0f;
        for (int i = 0; i < TOPK; i++) { const float e = expf(wts[i] - mx); wts[i] = e; s += e; }
        const float inv = 1.0f / s;
        for (int i = 0; i < TOPK; i++) wts[i] *= inv;
    }
    __syncthreads();

    __half* oh = aHi + row * LSEQ;
    for (int t = tid; t < LSEQ; t += 512) {
        float acc = 0.0f;
#pragma unroll
        for (int i = 0; i < TOPK; i++)
            acc += wts[i] * vbuf[(t + dly[i]) & (LSEQ - 1)];
        oh[t] = __float2half_rn(acc);
    }
}

// ---------------------------------------------------------------------------
// Launch
// ---------------------------------------------------------------------------
extern "C" void kernel_launch(void* const* d_in, const int* in_sizes, int n_in,
                              void* d_out, int out_size)
{
    const float* q  = (const float*)d_in[0];
    const float* k  = (const float*)d_in[1];
    const float* v  = (const float*)d_in[2];
    const float* Wq = (const float*)d_in[3];
    const float* bq = (const float*)d_in[4];
    const float* Wk = (const float*)d_in[5];
    const float* bk = (const float*)d_in[6];
    const float* Wv = (const float*)d_in[7];
    const float* bv = (const float*)d_in[8];
    const float* Wo = (const float*)d_in[9];
    const float* bo = (const float*)d_in[10];
    float* out = (float*)d_out;

    float  *qT, *kT, *vT;
    __half *ahi, *wthi, *wtlo;
    cudaGetSymbolAddress((void**)&qT,   g_qT);
    cudaGetSymbolAddress((void**)&kT,   g_kT);
    cudaGetSymbolAddress((void**)&vT,   g_vT);
    cudaGetSymbolAddress((void**)&ahi,  g_a_hi);
    cudaGetSymbolAddress((void**)&wthi, g_wt_hi);
    cudaGetSymbolAddress((void**)&wtlo, g_wt_lo);

    cudaFuncSetAttribute(hgemm_kernel<0,3>, cudaFuncAttributeMaxDynamicSharedMemorySize, GEMM_SMEM);
    cudaFuncSetAttribute(hgemm_kernel<0,2>, cudaFuncAttributeMaxDynamicSharedMemorySize, GEMM_SMEM);
    cudaFuncSetAttribute(hgemm_kernel<1,2>, cudaFuncAttributeMaxDynamicSharedMemorySize, GEMM_SMEM);
    cudaFuncSetAttribute(corr_kernel,       cudaFuncAttributeMaxDynamicSharedMemorySize, CORR_SMEM_BYTES);

    const int WSZ = DMODEL * DMODEL;
    wsplit_kernel<<<dim3(32, 32, 4), 256>>>(Wq, Wk, Wv, Wo, wthi, wtlo);

    const dim3 gg(DMODEL / 128, MTOT / 128);   // (8, 256)

    hgemm_kernel<0,3><<<gg, 256, GEMM_SMEM>>>(q, wthi + 0 * WSZ, wtlo + 0 * WSZ, bq, qT);
    hgemm_kernel<0,3><<<gg, 256, GEMM_SMEM>>>(k, wthi + 1 * WSZ, wtlo + 1 * WSZ, bk, kT);
    hgemm_kernel<0,2><<<gg, 256, GEMM_SMEM>>>(v, wthi + 2 * WSZ, wtlo + 2 * WSZ, bv, vT);

    corr_kernel<<<NROWS, 512, CORR_SMEM_BYTES>>>(qT, kT, vT, ahi);

    hgemm_kernel<1,2><<<gg, 256, GEMM_SMEM>>>(ahi, wthi + 3 * WSZ, wtlo + 3 * WSZ, bo, out);
}

// round 15
// speedup vs baseline: 1.1137x; 1.1137x over previous
#include <cuda_runtime.h>
#include <cuda_fp16.h>
#include <math.h>
#include <stdint.h>

#define NB      8
#define LSEQ    4096
#define DMODEL  1024
#define TOPK    16
#define NROWS   (NB * DMODEL)          // 8192
#define MTOT    (NB * LSEQ)            // 32768

// ---------------------------------------------------------------------------
// Scratch (device globals; no runtime allocation allowed)
// ---------------------------------------------------------------------------
__device__ float  g_qT[(size_t)NROWS * LSEQ];   // [b*1024 + hd][l] fp32
__device__ float  g_kT[(size_t)NROWS * LSEQ];
__device__ float  g_vT[(size_t)NROWS * LSEQ];
__device__ __half g_a_hi[(size_t)MTOT * DMODEL];   // agg, batched [(b*1024+hd)*4096+l]
__device__ __half g_wt_hi[4 * DMODEL * DMODEL];    // W^T, [n,k], 4 matrices
__device__ __half g_wt_lo[4 * DMODEL * DMODEL];

extern __shared__ char smem_raw[];

// ---------------------------------------------------------------------------
// PTX helpers (baseline sm_80+: cp.async / ldmatrix / mma)
// ---------------------------------------------------------------------------
__device__ __forceinline__ uint32_t smem_u32(const void* p) {
    uint32_t a;
    asm("{ .reg .u64 t; cvta.to.shared.u64 t, %1; cvt.u32.u64 %0, t; }" : "=r"(a) : "l"(p));
    return a;
}
__device__ __forceinline__ void cpa16(uint32_t d, const void* g) {
    asm volatile("cp.async.cg.shared.global [%0], [%1], 16;" :: "r"(d), "l"(g));
}
#define CPA_COMMIT() asm volatile("cp.async.commit_group;" ::: "memory")
#define CPA_WAIT(n)  asm volatile("cp.async.wait_group %0;" :: "n"(n) : "memory")

#define LDSM4(r0, r1, r2, r3, a) \
    asm volatile("ldmatrix.sync.aligned.m8n8.x4.shared.b16 {%0,%1,%2,%3}, [%4];" \
        : "=r"(r0), "=r"(r1), "=r"(r2), "=r"(r3) : "r"(a))

#define LDSM4T(r0, r1, r2, r3, a) \
    asm volatile("ldmatrix.sync.aligned.m8n8.x4.trans.shared.b16 {%0,%1,%2,%3}, [%4];" \
        : "=r"(r0), "=r"(r1), "=r"(r2), "=r"(r3) : "r"(a))

#define MMA16816(d, a, b) \
    asm volatile("mma.sync.aligned.m16n8k16.row.col.f32.f16.f16.f32 " \
        "{%0,%1,%2,%3}, {%4,%5,%6,%7}, {%8,%9}, {%0,%1,%2,%3};" \
        : "+f"((d)[0]), "+f"((d)[1]), "+f"((d)[2]), "+f"((d)[3]) \
        : "r"((a)[0]), "r"((a)[1]), "r"((a)[2]), "r"((a)[3]), "r"((b)[0]), "r"((b)[1]))

__device__ __forceinline__ uint32_t halves2u32(__half a, __half b) {
    __half2 h = __halves2half2(a, b);
    return *(uint32_t*)&h;
}
__device__ __forceinline__ float2 cmul(float2 a, float2 b) {
    return make_float2(a.x * b.x - a.y * b.y, a.x * b.y + a.y * b.x);
}

// ---------------------------------------------------------------------------
// Batched W [k,n] -> W^T [n,k] hi/lo split (blockIdx.z selects matrix)
// ---------------------------------------------------------------------------
__global__ void __launch_bounds__(256) wsplit_kernel(
    const float* __restrict__ W0, const float* __restrict__ W1,
    const float* __restrict__ W2, const float* __restrict__ W3,
    __half* __restrict__ Thi, __half* __restrict__ Tlo)
{
    const float* W = (blockIdx.z == 0) ? W0 : (blockIdx.z == 1) ? W1
                   : (blockIdx.z == 2) ? W2 : W3;
    __half* hi = Thi + (size_t)blockIdx.z * DMODEL * DMODEL;
    __half* lo = Tlo + (size_t)blockIdx.z * DMODEL * DMODEL;

    __shared__ float t[32][33];
    const int bx = blockIdx.x * 32;
    const int by = blockIdx.y * 32;
    const int tx = threadIdx.x & 31;
    const int ty = threadIdx.x >> 5;
#pragma unroll
    for (int j = 0; j < 4; j++)
        t[ty + j * 8][tx] = W[(size_t)(by + ty + j * 8) * DMODEL + bx + tx];
    __syncthreads();
#pragma unroll
    for (int j = 0; j < 4; j++) {
        const float v = t[tx][ty + j * 8];
        const __half h = __float2half_rn(v);
        const size_t o = (size_t)(bx + ty + j * 8) * DMODEL + by + tx;
        hi[o] = h;
        lo[o] = __float2half_rn(v - __half2float(h));
    }
}

// ---------------------------------------------------------------------------
// Split-fp16 HMMA GEMM (R12 config: f32 acc, K-slab 32, (256,2), regs 127)
// PASSES=3: acc = Ah*Bh + Ah*Bl + Al*Bh ; PASSES=2: acc = Ah*Bh + Ah*Bl
// MODE 0: A fp32 row-major, split in-kernel; C batched-transposed fp32.
// MODE 1: A fp16 hi batched [(b*1024+k)*4096+l], ldmatrix.trans; C row-major.
// ---------------------------------------------------------------------------
#define SA    0
#define SB    16384
#define STAGE 32768
#define GEMM_SMEM 67584
#define EPS 132

__device__ __forceinline__ int swz(int r, int cb) {     // 128B rows
    return r * 128 + (cb ^ ((r & 7) << 4));
}
__device__ __forceinline__ int swz256(int r, int cb) {  // 256B rows (MODE1 A)
    return r * 256 + (cb ^ ((r & 7) << 4));
}

template<int MODE, int PASSES>
__global__ void __launch_bounds__(256, 2) hgemm_kernel(
    const void* __restrict__ Ain,
    const __half* __restrict__ Bhi, const __half* __restrict__ Blo,
    const float* __restrict__ bias, float* __restrict__ C)
{
    char* smem = smem_raw;
    const int tid  = threadIdx.x;
    const int wid  = tid >> 5;
    const int lane = tid & 31;
    const int n0 = blockIdx.x * 128;
    const int m0 = blockIdx.y * 128;
    const int warp_m = wid & 1;
    const int warp_n = wid >> 1;
    const int bb = m0 >> 12;
    const int l0 = m0 & (LSEQ - 1);
    const uint32_t sbase = smem_u32(smem);

    const float*  Af = (const float*)Ain;    // MODE 0
    const __half* Ah = (const __half*)Ain;   // MODE 1

    float acc[4][4][4];
#pragma unroll
    for (int mi = 0; mi < 4; mi++)
#pragma unroll
        for (int ni = 0; ni < 4; ni++)
#pragma unroll
            for (int j = 0; j < 4; j++) acc[mi][ni][j] = 0.0f;

    float4 ar[4];   // MODE 0 prefetch

    auto loadStage = [&](int st, int kt) {
        const uint32_t sb = sbase + st * STAGE;
#pragma unroll
        for (int i = 0; i < 4; i++) {
            const int idx = tid + i * 256;
            const int rr = idx >> 3, ch = idx & 7;
            const bool ishi = (ch < 4);
            const int c4 = ch & 3;
            const __half* src = (ishi ? Bhi : Blo) + (size_t)(n0 + rr) * DMODEL + kt + c4 * 8;
            cpa16(sb + SB + swz(rr, (ishi ? 0 : 64) + c4 * 16), src);
        }
        if (MODE == 1) {
#pragma unroll
            for (int i = 0; i < 2; i++) {
                const int idx = tid + i * 256;
                const int rr = idx >> 4;
                const int ch = idx & 15;
                const __half* src = Ah + ((size_t)(bb * DMODEL + kt + rr)) * LSEQ + l0 + ch * 8;
                cpa16(sb + SA + swz256(rr, ch * 16), src);
            }
        }
        CPA_COMMIT();
    };

    auto ldgA = [&](int kt) {
        if (MODE == 0) {
#pragma unroll
            for (int j = 0; j < 4; j++) {
                const int c = tid + j * 256;
                const int rr = c >> 3, c4 = c & 7;
                ar[j] = *(const float4*)(Af + (size_t)(m0 + rr) * DMODEL + kt + c4 * 4);
            }
        }
    };

    auto stsA = [&](int st) {
        if (MODE == 0) {
            char* buf = smem + st * STAGE + SA;
#pragma unroll
            for (int j = 0; j < 4; j++) {
                const int c = tid + j * 256;
                const int rr = c >> 3, c4 = c & 7;
                const float4 v = ar[j];
                const __half h0 = __float2half_rn(v.x);
                const __half h1 = __float2half_rn(v.y);
                const __half h2 = __float2half_rn(v.z);
                const __half h3 = __float2half_rn(v.w);
                const int xo = ((rr & 7) << 4);
                const int half8 = (c4 & 1) * 8;
                uint2 hh;
                hh.x = halves2u32(h0, h1);
                hh.y = halves2u32(h2, h3);
                *(uint2*)(buf + rr * 128 + (((c4 >> 1) * 16) ^ xo) + half8) = hh;
                if (PASSES == 3) {
                    uint2 ll;
                    ll.x = halves2u32(__float2half_rn(v.x - __half2float(h0)),
                                      __float2half_rn(v.y - __half2float(h1)));
                    ll.y = halves2u32(__float2half_rn(v.z - __half2float(h2)),
                                      __float2half_rn(v.w - __half2float(h3)));
                    *(uint2*)(buf + rr * 128 + ((64 + (c4 >> 1) * 16) ^ xo) + half8) = ll;
                }
            }
        }
    };

    loadStage(0, 0);
    ldgA(0);
    stsA(0);

    for (int s = 0; s < 32; s++) {
        if (s < 31) { loadStage((s + 1) & 1, (s + 1) * 32); ldgA((s + 1) * 32); }
        if (s < 31) { CPA_WAIT(1); } else { CPA_WAIT(0); }
        __syncthreads();

        const uint32_t sb = sbase + (s & 1) * STAGE;
#pragma unroll
        for (int kk = 0; kk < 2; kk++) {
            uint32_t ahi[4][4], alo[4][4], bhi[4][2], blo[4][2];
            if (MODE == 0) {
                const int arr = warp_m * 64 + (lane & 15);
                const int acb = kk * 32 + (lane >> 4) * 16;
#pragma unroll
                for (int mi = 0; mi < 4; mi++) {
                    const int r = arr + mi * 16;
                    LDSM4(ahi[mi][0], ahi[mi][1], ahi[mi][2], ahi[mi][3], sb + SA + swz(r, acb));
                    if (PASSES == 3)
                        LDSM4(alo[mi][0], alo[mi][1], alo[mi][2], alo[mi][3],
                              sb + SA + swz(r, 64 + acb));
                }
            } else {
                const int krow = kk * 16 + (lane & 7) + ((lane >> 4) & 1) * 8;
                const int mcb0 = (warp_m * 64) * 2 + ((lane >> 3) & 1) * 16;
#pragma unroll
                for (int mi = 0; mi < 4; mi++)
                    LDSM4T(ahi[mi][0], ahi[mi][1], ahi[mi][2], ahi[mi][3],
                           sb + SA + swz256(krow, mcb0 + mi * 32));
            }
            const int br = warp_n * 32 + ((lane >> 4) << 3) + (lane & 7);
            const int bcb = kk * 32 + ((lane >> 3) & 1) * 16;
#pragma unroll
            for (int ni2 = 0; ni2 < 2; ni2++) {
                const int r = br + ni2 * 16;
                LDSM4(bhi[ni2 * 2][0], bhi[ni2 * 2][1], bhi[ni2 * 2 + 1][0], bhi[ni2 * 2 + 1][1],
                      sb + SB + swz(r, bcb));
                LDSM4(blo[ni2 * 2][0], blo[ni2 * 2][1], blo[ni2 * 2 + 1][0], blo[ni2 * 2 + 1][1],
                      sb + SB + swz(r, 64 + bcb));
            }
#pragma unroll
            for (int mi = 0; mi < 4; mi++)
#pragma unroll
                for (int ni = 0; ni < 4; ni++)
                    MMA16816(acc[mi][ni], ahi[mi], bhi[ni]);
#pragma unroll
            for (int mi = 0; mi < 4; mi++)
#pragma unroll
                for (int ni = 0; ni < 4; ni++)
                    MMA16816(acc[mi][ni], ahi[mi], blo[ni]);
            if (PASSES == 3) {
#pragma unroll
                for (int mi = 0; mi < 4; mi++)
#pragma unroll
                    for (int ni = 0; ni < 4; ni++)
                        MMA16816(acc[mi][ni], alo[mi], bhi[ni]);
            }
        }
        if (s < 31) stsA((s + 1) & 1);
        __syncthreads();
    }

    // ---- epilogue via smem for coalesced stores ----
    float* ep = (float*)smem;
#pragma unroll
    for (int mi = 0; mi < 4; mi++) {
        const int r0 = warp_m * 64 + mi * 16 + (lane >> 2);
#pragma unroll
        for (int ni = 0; ni < 4; ni++) {
            const int c = warp_n * 32 + ni * 8 + 2 * (lane & 3);
            const float b0 = bias[n0 + c];
            const float b1 = bias[n0 + c + 1];
            if (MODE == 0) {
                ep[(c    ) * EPS + r0    ] = acc[mi][ni][0] + b0;
                ep[(c + 1) * EPS + r0    ] = acc[mi][ni][1] + b1;
                ep[(c    ) * EPS + r0 + 8] = acc[mi][ni][2] + b0;
                ep[(c + 1) * EPS + r0 + 8] = acc[mi][ni][3] + b1;
            } else {
                ep[(r0    ) * EPS + c    ] = acc[mi][ni][0] + b0;
                ep[(r0    ) * EPS + c + 1] = acc[mi][ni][1] + b1;
                ep[(r0 + 8) * EPS + c    ] = acc[mi][ni][2] + b0;
                ep[(r0 + 8) * EPS + c + 1] = acc[mi][ni][3] + b1;
            }
        }
    }
    __syncthreads();
#pragma unroll
    for (int j = 0; j < 16; j++) {
        const int row = j * 8 + wid;
        const float4 v = *(const float4*)(ep + row * EPS + lane * 4);
        if (MODE == 0)
            *(float4*)(C + ((size_t)(bb * DMODEL + n0 + row)) * LSEQ + l0 + lane * 4) = v;
        else
            *(float4*)(C + (size_t)(m0 + row) * DMODEL + n0 + lane * 4) = v;
    }
}

// ---------------------------------------------------------------------------
// Fused correlation kernel: radix-8 FFT; FFT2 stage0 fused with spectrum pass.
// 64KB smem. Result of FFT2 lands in Az; vbuf aliases Bz.
// ---------------------------------------------------------------------------
#define CORR_SMEM_BYTES (2 * LSEQ * 8 + 64 * 4)

__device__ __forceinline__ void radix8_store(
    float2* dst, const float2* x, int Jm, int k, int m)
{
    const float C707 = 0.70710678118654752f;
    const float2 x0 = x[0], x1 = x[1], x2 = x[2], x3 = x[3];
    const float2 x4 = x[4], x5 = x[5], x6 = x[6], x7 = x[7];
    const float a0x = x0.x + x4.x, a0y = x0.y + x4.y;
    const float a1x = x0.x - x4.x, a1y = x0.y - x4.y;
    const float b0x = x2.x + x6.x, b0y = x2.y + x6.y;
    const float b1x = x2.x - x6.x, b1y = x2.y - x6.y;
    const float E0x = a0x + b0x, E0y = a0y + b0y;
    const float E1x = a1x + b1y, E1y = a1y - b1x;
    const float E2x = a0x - b0x, E2y = a0y - b0y;
    const float E3x = a1x - b1y, E3y = a1y + b1x;
    const float c0x = x1.x + x5.x, c0y = x1.y + x5.y;
    const float c1x = x1.x - x5.x, c1y = x1.y - x5.y;
    const float d0x = x3.x + x7.x, d0y = x3.y + x7.y;
    const float d1x = x3.x - x7.x, d1y = x3.y - x7.y;
    const float O0x = c0x + d0x, O0y = c0y + d0y;
    const float O1x = c1x + d1y, O1y = c1y - d1x;
    const float O2x = c0x - d0x, O2y = c0y - d0y;
    const float O3x = c1x - d1y, O3y = c1y + d1x;
    const float t1x = C707 * (O1x + O1y), t1y = C707 * (O1y - O1x);
    const float t2x = O2y,               t2y = -O2x;
    const float t3x = C707 * (O3y - O3x), t3y = -C707 * (O3x + O3y);
    const float2 y0 = make_float2(E0x + O0x, E0y + O0y);
    const float2 y4 = make_float2(E0x - O0x, E0y - O0y);
    const float2 y1 = make_float2(E1x + t1x, E1y + t1y);
    const float2 y5 = make_float2(E1x - t1x, E1y - t1y);
    const float2 y2 = make_float2(E2x + t2x, E2y + t2y);
    const float2 y6 = make_float2(E2x - t2x, E2y - t2y);
    const float2 y3 = make_float2(E3x + t3x, E3y + t3y);
    const float2 y7 = make_float2(E3x - t3x, E3y - t3y);
    const float ang = -1.5339807878856412e-3f * (float)Jm;
    float s1, cc1;
    __sincosf(ang, &s1, &cc1);
    const float2 w1 = make_float2(cc1, s1);
    const float2 w2 = cmul(w1, w1);
    const float2 w3 = cmul(w2, w1);
    const float2 w4 = cmul(w2, w2);
    const float2 w5 = cmul(w3, w2);
    const float2 w6 = cmul(w3, w3);
    const float2 w7 = cmul(w4, w3);
    const int base = 8 * Jm + k;
    dst[base]         = y0;
    dst[base + m]     = cmul(y1, w1);
    dst[base + 2 * m] = cmul(y2, w2);
    dst[base + 3 * m] = cmul(y3, w3);
    dst[base + 4 * m] = cmul(y4, w4);
    dst[base + 5 * m] = cmul(y5, w5);
    dst[base + 6 * m] = cmul(y6, w6);
    dst[base + 7 * m] = cmul(y7, w7);
}

__device__ __forceinline__ void fft4096(float2* buf0, float2* buf1, int tid)
{
    float2* src = buf0;
    float2* dst = buf1;
    int m = 1;
    for (int st = 0; st < 4; st++) {
        __syncthreads();
        const int k  = tid & (m - 1);
        const int Jm = tid - k;
        float2 x[8];
#pragma unroll
        for (int p = 0; p < 8; p++) x[p] = src[tid + 512 * p];
        radix8_store(dst, x, Jm, k, m);
        float2* t = src; src = dst; dst = t;
        m <<= 3;
    }
    __syncthreads();
}

// spectrum of the packed z-FFT: S(f) = conj(Q(f) * conj(K(f)))
__device__ __forceinline__ float2 spec_at(const float2* Az, int f)
{
    const float2 zf = Az[f];
    const float2 zc = Az[(LSEQ - f) & (LSEQ - 1)];
    const float qx = 0.5f * (zf.x + zc.x);
    const float qy = 0.5f * (zf.y - zc.y);
    const float dx = 0.5f * (zf.x - zc.x);
    const float dy = 0.5f * (zf.y + zc.y);
    const float kx = dy;
    const float ky = -dx;
    return make_float2(qx * kx + qy * ky, -(qy * kx - qx * ky));
}

// FFT of the spectrum, stage0 fused (reads Z from Az on the fly).
// Stage writes: Bz, Az, Bz, Az  -> final result in Az.
__device__ __forceinline__ void fft4096_spec(float2* Az, float2* Bz, int tid)
{
    // stage 0 (m=1, k=0, Jm=tid): inputs computed from spectrum of Az
    {
        float2 x[8];
#pragma unroll
        for (int p = 0; p < 8; p++) x[p] = spec_at(Az, tid + 512 * p);
        radix8_store(Bz, x, tid, 0, 1);
    }
    // stages 1..3
    float2* src = Bz;
    float2* dst = Az;
    int m = 8;
    for (int st = 0; st < 3; st++) {
        __syncthreads();
        const int k  = tid & (m - 1);
        const int Jm = tid - k;
        float2 x[8];
#pragma unroll
        for (int p = 0; p < 8; p++) x[p] = src[tid + 512 * p];
        radix8_store(dst, x, Jm, k, m);
        float2* t = src; src = dst; dst = t;
        m <<= 3;
    }
    __syncthreads();
}

__global__ void __launch_bounds__(512, 2) corr_kernel(
    const float* __restrict__ qT, const float* __restrict__ kT,
    const float* __restrict__ vT, __half* __restrict__ aHi)
{
    float* smem = (float*)smem_raw;
    float2* Az   = (float2*)smem;          // FFT2 result lands here
    float2* Bz   = Az + LSEQ;              // reused as vbuf after FFT2
    float*  tail = (float*)(Bz + LSEQ);
    float*  rval = tail;                   // 16
    int*    ridx = (int*)(rval + 16);      // 16
    float*  wts  = (float*)(ridx + 16);    // 16
    int*    dly  = (int*)(wts + 16);       // 16
    float*  vbuf = (float*)Bz;             // alias (valid after FFT2)

    const int tid = threadIdx.x;
    const size_t row = blockIdx.x;
    const float* qp = qT + row * LSEQ;
    const float* kp = kT + row * LSEQ;
    const float* vp = vT + row * LSEQ;

#pragma unroll
    for (int i4 = tid; i4 < LSEQ / 4; i4 += 512) {
        const float4 q4 = ((const float4*)qp)[i4];
        const float4 k4 = ((const float4*)kp)[i4];
        Az[i4 * 4 + 0] = make_float2(q4.x, k4.x);
        Az[i4 * 4 + 1] = make_float2(q4.y, k4.y);
        Az[i4 * 4 + 2] = make_float2(q4.z, k4.z);
        Az[i4 * 4 + 3] = make_float2(q4.w, k4.w);
    }

    fft4096(Az, Bz, tid);        // Z = fft(q + i k), result in Az
    fft4096_spec(Az, Bz, tid);   // corr*N = Re(fft(S)), result in Az

    // pull corr values into registers BEFORE overwriting Bz with v
    float cv[8];
#pragma unroll
    for (int c = 0; c < 8; c++) cv[c] = Az[tid + 512 * c].x;

    // stream v into the Bz region (completion covered by topk-loop syncs)
#pragma unroll
    for (int i4 = tid; i4 < LSEQ / 4; i4 += 512)
        *(float4*)(vbuf + i4 * 4) = ((const float4*)vp)[i4];

    // ---- register-resident top-16 with block-sync merge ----
    const int lane = tid & 31;
    const int wrp  = tid >> 5;
    for (int it = 0; it < TOPK; it++) {
        float best = cv[0];
        int   bc   = 0;
#pragma unroll
        for (int c = 1; c < 8; c++)
            if (cv[c] > best) { best = cv[c]; bc = c; }
        int bi = tid + 512 * bc;
#pragma unroll
        for (int off = 16; off; off >>= 1) {
            const float ov = __shfl_down_sync(0xffffffffu, best, off);
            const int   oi = __shfl_down_sync(0xffffffffu, bi, off);
            if (ov > best || (ov == best && oi < bi)) { best = ov; bi = oi; }
        }
        if (lane == 0) { rval[wrp] = best; ridx[wrp] = bi; }
        __syncthreads();
        if (tid < 32) {
            float v = (lane < 16) ? rval[lane] : -INFINITY;
            int   i = (lane < 16) ? ridx[lane] : LSEQ;
#pragma unroll
            for (int off = 8; off; off >>= 1) {
                const float ov = __shfl_down_sync(0xffffffffu, v, off);
                const int   oi = __shfl_down_sync(0xffffffffu, i, off);
                if (ov > v || (ov == v && oi < i)) { v = ov; i = oi; }
            }
            if (lane == 0) { wts[it] = v * (1.0f / (float)LSEQ); dly[it] = i; }
        }
        __syncthreads();
        const int gi = dly[it];
        if (tid == (gi & 511)) cv[gi >> 9] = -INFINITY;
    }

    if (tid == 0) {
        float mx = wts[0];
        for (int i = 1; i < TOPK; i++) mx = fmaxf(mx, wts[i]);
        float s = 0.0f;
        for (int i = 0; i < TOPK; i++) { const float e = expf(wts[i] - mx); wts[i] = e; s += e; }
        const float inv = 1.0f / s;
        for (int i = 0; i < TOPK; i++) wts[i] *= inv;
    }
    __syncthreads();

    __half* oh = aHi + row * LSEQ;
    for (int t = tid; t < LSEQ; t += 512) {
        float acc = 0.0f;
#pragma unroll
        for (int i = 0; i < TOPK; i++)
            acc += wts[i] * vbuf[(t + dly[i]) & (LSEQ - 1)];
        oh[t] = __float2half_rn(acc);
    }
}

// ---------------------------------------------------------------------------
// Launch
// ---------------------------------------------------------------------------
extern "C" void kernel_launch(void* const* d_in, const int* in_sizes, int n_in,
                              void* d_out, int out_size)
{
    const float* q  = (const float*)d_in[0];
    const float* k  = (const float*)d_in[1];
    const float* v  = (const float*)d_in[2];
    const float* Wq = (const float*)d_in[3];
    const float* bq = (const float*)d_in[4];
    const float* Wk = (const float*)d_in[5];
    const float* bk = (const float*)d_in[6];
    const float* Wv = (const float*)d_in[7];
    const float* bv = (const float*)d_in[8];
    const float* Wo = (const float*)d_in[9];
    const float* bo = (const float*)d_in[10];
    float* out = (float*)d_out;

    float  *qT, *kT, *vT;
    __half *ahi, *wthi, *wtlo;
    cudaGetSymbolAddress((void**)&qT,   g_qT);
    cudaGetSymbolAddress((void**)&kT,   g_kT);
    cudaGetSymbolAddress((void**)&vT,   g_vT);
    cudaGetSymbolAddress((void**)&ahi,  g_a_hi);
    cudaGetSymbolAddress((void**)&wthi, g_wt_hi);
    cudaGetSymbolAddress((void**)&wtlo, g_wt_lo);

    cudaFuncSetAttribute(hgemm_kernel<0,3>, cudaFuncAttributeMaxDynamicSharedMemorySize, GEMM_SMEM);
    cudaFuncSetAttribute(hgemm_kernel<0,2>, cudaFuncAttributeMaxDynamicSharedMemorySize, GEMM_SMEM);
    cudaFuncSetAttribute(hgemm_kernel<1,2>, cudaFuncAttributeMaxDynamicSharedMemorySize, GEMM_SMEM);
    cudaFuncSetAttribute(corr_kernel,       cudaFuncAttributeMaxDynamicSharedMemorySize, CORR_SMEM_BYTES);

    const int WSZ = DMODEL * DMODEL;
    wsplit_kernel<<<dim3(32, 32, 4), 256>>>(Wq, Wk, Wv, Wo, wthi, wtlo);

    const dim3 gg(DMODEL / 128, MTOT / 128);   // (8, 256)

    hgemm_kernel<0,3><<<gg, 256, GEMM_SMEM>>>(q, wthi + 0 * WSZ, wtlo + 0 * WSZ, bq, qT);
    hgemm_kernel<0,3><<<gg, 256, GEMM_SMEM>>>(k, wthi + 1 * WSZ, wtlo + 1 * WSZ, bk, kT);
    hgemm_kernel<0,2><<<gg, 256, GEMM_SMEM>>>(v, wthi + 2 * WSZ, wtlo + 2 * WSZ, bv, vT);

    corr_kernel<<<NROWS, 512, CORR_SMEM_BYTES>>>(qT, kT, vT, ahi);

    hgemm_kernel<1,2><<<gg, 256, GEMM_SMEM>>>(ahi, wthi + 3 * WSZ, wtlo + 3 * WSZ, bo, out);
}

// round 16
// speedup vs baseline: 1.2645x; 1.1354x over previous
#include <cuda_runtime.h>
#include <cuda_fp16.h>
#include <math.h>
#include <stdint.h>

#define NB      8
#define LSEQ    4096
#define DMODEL  1024
#define TOPK    16
#define NROWS   (NB * DMODEL)          // 8192
#define MTOT    (NB * LSEQ)            // 32768

// ---------------------------------------------------------------------------
// Scratch (device globals; no runtime allocation allowed)
// ---------------------------------------------------------------------------
__device__ float  g_qT[(size_t)NROWS * LSEQ];   // [b*1024 + hd][l] fp32
__device__ float  g_kT[(size_t)NROWS * LSEQ];
__device__ float  g_vT[(size_t)NROWS * LSEQ];
__device__ __half g_a_hi[(size_t)MTOT * DMODEL];   // agg, batched [(b*1024+hd)*4096+l]
__device__ __half g_wt_hi[4 * DMODEL * DMODEL];    // W^T, [n,k], 4 matrices
__device__ __half g_wt_lo[4 * DMODEL * DMODEL];

extern __shared__ char smem_raw[];

// ---------------------------------------------------------------------------
// PTX helpers (baseline sm_80+: cp.async / ldmatrix / mma)
// ---------------------------------------------------------------------------
__device__ __forceinline__ uint32_t smem_u32(const void* p) {
    uint32_t a;
    asm("{ .reg .u64 t; cvta.to.shared.u64 t, %1; cvt.u32.u64 %0, t; }" : "=r"(a) : "l"(p));
    return a;
}
__device__ __forceinline__ void cpa16(uint32_t d, const void* g) {
    asm volatile("cp.async.cg.shared.global [%0], [%1], 16;" :: "r"(d), "l"(g));
}
#define CPA_COMMIT() asm volatile("cp.async.commit_group;" ::: "memory")
#define CPA_WAIT(n)  asm volatile("cp.async.wait_group %0;" :: "n"(n) : "memory")

#define LDSM4(r0, r1, r2, r3, a) \
    asm volatile("ldmatrix.sync.aligned.m8n8.x4.shared.b16 {%0,%1,%2,%3}, [%4];" \
        : "=r"(r0), "=r"(r1), "=r"(r2), "=r"(r3) : "r"(a))

#define LDSM4T(r0, r1, r2, r3, a) \
    asm volatile("ldmatrix.sync.aligned.m8n8.x4.trans.shared.b16 {%0,%1,%2,%3}, [%4];" \
        : "=r"(r0), "=r"(r1), "=r"(r2), "=r"(r3) : "r"(a))

#define MMA16816(d, a, b) \
    asm volatile("mma.sync.aligned.m16n8k16.row.col.f32.f16.f16.f32 " \
        "{%0,%1,%2,%3}, {%4,%5,%6,%7}, {%8,%9}, {%0,%1,%2,%3};" \
        : "+f"((d)[0]), "+f"((d)[1]), "+f"((d)[2]), "+f"((d)[3]) \
        : "r"((a)[0]), "r"((a)[1]), "r"((a)[2]), "r"((a)[3]), "r"((b)[0]), "r"((b)[1]))

__device__ __forceinline__ uint32_t halves2u32(__half a, __half b) {
    __half2 h = __halves2half2(a, b);
    return *(uint32_t*)&h;
}
__device__ __forceinline__ float2 cmul(float2 a, float2 b) {
    return make_float2(a.x * b.x - a.y * b.y, a.x * b.y + a.y * b.x);
}

// ---------------------------------------------------------------------------
// Batched W [k,n] -> W^T [n,k] hi/lo split (blockIdx.z selects matrix)
// ---------------------------------------------------------------------------
__global__ void __launch_bounds__(256) wsplit_kernel(
    const float* __restrict__ W0, const float* __restrict__ W1,
    const float* __restrict__ W2, const float* __restrict__ W3,
    __half* __restrict__ Thi, __half* __restrict__ Tlo)
{
    const float* W = (blockIdx.z == 0) ? W0 : (blockIdx.z == 1) ? W1
                   : (blockIdx.z == 2) ? W2 : W3;
    __half* hi = Thi + (size_t)blockIdx.z * DMODEL * DMODEL;
    __half* lo = Tlo + (size_t)blockIdx.z * DMODEL * DMODEL;

    __shared__ float t[32][33];
    const int bx = blockIdx.x * 32;
    const int by = blockIdx.y * 32;
    const int tx = threadIdx.x & 31;
    const int ty = threadIdx.x >> 5;
#pragma unroll
    for (int j = 0; j < 4; j++)
        t[ty + j * 8][tx] = W[(size_t)(by + ty + j * 8) * DMODEL + bx + tx];
    __syncthreads();
#pragma unroll
    for (int j = 0; j < 4; j++) {
        const float v = t[tx][ty + j * 8];
        const __half h = __float2half_rn(v);
        const size_t o = (size_t)(bx + ty + j * 8) * DMODEL + by + tx;
        hi[o] = h;
        lo[o] = __float2half_rn(v - __half2float(h));
    }
}

// ---------------------------------------------------------------------------
// Split-fp16 HMMA GEMM (f32 acc, K-slab 32, (256,2))
// PASSES=3: acc = Ah*Bh + Ah*Bl + Al*Bh  (q,k — feed softmax logits)
// PASSES=2: acc = Ah*Bh + Ah*Bl
// PASSES=1: acc = Ah*Bh                  (v, out — pure linear perturbation)
// MODE 0: A fp32 row-major, split in-kernel; C batched-transposed fp32.
// MODE 1: A fp16 hi batched [(b*1024+k)*4096+l], ldmatrix.trans; C row-major.
// ---------------------------------------------------------------------------
#define SA    0
#define SB    16384
#define STAGE 32768
#define GEMM_SMEM 67584
#define EPS 132

__device__ __forceinline__ int swz(int r, int cb) {     // 128B rows
    return r * 128 + (cb ^ ((r & 7) << 4));
}
__device__ __forceinline__ int swz256(int r, int cb) {  // 256B rows (MODE1 A)
    return r * 256 + (cb ^ ((r & 7) << 4));
}

template<int MODE, int PASSES>
__global__ void __launch_bounds__(256, 2) hgemm_kernel(
    const void* __restrict__ Ain,
    const __half* __restrict__ Bhi, const __half* __restrict__ Blo,
    const float* __restrict__ bias, float* __restrict__ C)
{
    char* smem = smem_raw;
    const int tid  = threadIdx.x;
    const int wid  = tid >> 5;
    const int lane = tid & 31;
    const int n0 = blockIdx.x * 128;
    const int m0 = blockIdx.y * 128;
    const int warp_m = wid & 1;
    const int warp_n = wid >> 1;
    const int bb = m0 >> 12;
    const int l0 = m0 & (LSEQ - 1);
    const uint32_t sbase = smem_u32(smem);

    const float*  Af = (const float*)Ain;    // MODE 0
    const __half* Ah = (const __half*)Ain;   // MODE 1

    float acc[4][4][4];
#pragma unroll
    for (int mi = 0; mi < 4; mi++)
#pragma unroll
        for (int ni = 0; ni < 4; ni++)
#pragma unroll
            for (int j = 0; j < 4; j++) acc[mi][ni][j] = 0.0f;

    float4 ar[4];   // MODE 0 prefetch

    auto loadStage = [&](int st, int kt) {
        const uint32_t sb = sbase + st * STAGE;
        if (PASSES == 1) {
            // B hi only: 128 rows x 64B = 512 chunks
#pragma unroll
            for (int i = 0; i < 2; i++) {
                const int idx = tid + i * 256;
                const int rr = idx >> 2, c4 = idx & 3;
                cpa16(sb + SB + swz(rr, c4 * 16),
                      Bhi + (size_t)(n0 + rr) * DMODEL + kt + c4 * 8);
            }
        } else {
#pragma unroll
            for (int i = 0; i < 4; i++) {
                const int idx = tid + i * 256;
                const int rr = idx >> 3, ch = idx & 7;
                const bool ishi = (ch < 4);
                const int c4 = ch & 3;
                const __half* src = (ishi ? Bhi : Blo) + (size_t)(n0 + rr) * DMODEL + kt + c4 * 8;
                cpa16(sb + SB + swz(rr, (ishi ? 0 : 64) + c4 * 16), src);
            }
        }
        if (MODE == 1) {
#pragma unroll
            for (int i = 0; i < 2; i++) {
                const int idx = tid + i * 256;
                const int rr = idx >> 4;
                const int ch = idx & 15;
                const __half* src = Ah + ((size_t)(bb * DMODEL + kt + rr)) * LSEQ + l0 + ch * 8;
                cpa16(sb + SA + swz256(rr, ch * 16), src);
            }
        }
        CPA_COMMIT();
    };

    auto ldgA = [&](int kt) {
        if (MODE == 0) {
#pragma unroll
            for (int j = 0; j < 4; j++) {
                const int c = tid + j * 256;
                const int rr = c >> 3, c4 = c & 7;
                ar[j] = *(const float4*)(Af + (size_t)(m0 + rr) * DMODEL + kt + c4 * 4);
            }
        }
    };

    auto stsA = [&](int st) {
        if (MODE == 0) {
            char* buf = smem + st * STAGE + SA;
#pragma unroll
            for (int j = 0; j < 4; j++) {
                const int c = tid + j * 256;
                const int rr = c >> 3, c4 = c & 7;
                const float4 v = ar[j];
                const __half h0 = __float2half_rn(v.x);
                const __half h1 = __float2half_rn(v.y);
                const __half h2 = __float2half_rn(v.z);
                const __half h3 = __float2half_rn(v.w);
                const int xo = ((rr & 7) << 4);
                const int half8 = (c4 & 1) * 8;
                uint2 hh;
                hh.x = halves2u32(h0, h1);
                hh.y = halves2u32(h2, h3);
                *(uint2*)(buf + rr * 128 + (((c4 >> 1) * 16) ^ xo) + half8) = hh;
                if (PASSES == 3) {
                    uint2 ll;
                    ll.x = halves2u32(__float2half_rn(v.x - __half2float(h0)),
                                      __float2half_rn(v.y - __half2float(h1)));
                    ll.y = halves2u32(__float2half_rn(v.z - __half2float(h2)),
                                      __float2half_rn(v.w - __half2float(h3)));
                    *(uint2*)(buf + rr * 128 + ((64 + (c4 >> 1) * 16) ^ xo) + half8) = ll;
                }
            }
        }
    };

    loadStage(0, 0);
    ldgA(0);
    stsA(0);

    for (int s = 0; s < 32; s++) {
        if (s < 31) { loadStage((s + 1) & 1, (s + 1) * 32); ldgA((s + 1) * 32); }
        if (s < 31) { CPA_WAIT(1); } else { CPA_WAIT(0); }
        __syncthreads();

        const uint32_t sb = sbase + (s & 1) * STAGE;
#pragma unroll
        for (int kk = 0; kk < 2; kk++) {
            uint32_t ahi[4][4], alo[4][4], bhi[4][2], blo[4][2];
            if (MODE == 0) {
                const int arr = warp_m * 64 + (lane & 15);
                const int acb = kk * 32 + (lane >> 4) * 16;
#pragma unroll
                for (int mi = 0; mi < 4; mi++) {
                    const int r = arr + mi * 16;
                    LDSM4(ahi[mi][0], ahi[mi][1], ahi[mi][2], ahi[mi][3], sb + SA + swz(r, acb));
                    if (PASSES == 3)
                        LDSM4(alo[mi][0], alo[mi][1], alo[mi][2], alo[mi][3],
                              sb + SA + swz(r, 64 + acb));
                }
            } else {
                const int krow = kk * 16 + (lane & 7) + ((lane >> 4) & 1) * 8;
                const int mcb0 = (warp_m * 64) * 2 + ((lane >> 3) & 1) * 16;
#pragma unroll
                for (int mi = 0; mi < 4; mi++)
                    LDSM4T(ahi[mi][0], ahi[mi][1], ahi[mi][2], ahi[mi][3],
                           sb + SA + swz256(krow, mcb0 + mi * 32));
            }
            const int br = warp_n * 32 + ((lane >> 4) << 3) + (lane & 7);
            const int bcb = kk * 32 + ((lane >> 3) & 1) * 16;
#pragma unroll
            for (int ni2 = 0; ni2 < 2; ni2++) {
                const int r = br + ni2 * 16;
                LDSM4(bhi[ni2 * 2][0], bhi[ni2 * 2][1], bhi[ni2 * 2 + 1][0], bhi[ni2 * 2 + 1][1],
                      sb + SB + swz(r, bcb));
                if (PASSES >= 2)
                    LDSM4(blo[ni2 * 2][0], blo[ni2 * 2][1], blo[ni2 * 2 + 1][0], blo[ni2 * 2 + 1][1],
                          sb + SB + swz(r, 64 + bcb));
            }
#pragma unroll
            for (int mi = 0; mi < 4; mi++)
#pragma unroll
                for (int ni = 0; ni < 4; ni++)
                    MMA16816(acc[mi][ni], ahi[mi], bhi[ni]);
            if (PASSES >= 2) {
#pragma unroll
                for (int mi = 0; mi < 4; mi++)
#pragma unroll
                    for (int ni = 0; ni < 4; ni++)
                        MMA16816(acc[mi][ni], ahi[mi], blo[ni]);
            }
            if (PASSES == 3) {
#pragma unroll
                for (int mi = 0; mi < 4; mi++)
#pragma unroll
                    for (int ni = 0; ni < 4; ni++)
                        MMA16816(acc[mi][ni], alo[mi], bhi[ni]);
            }
        }
        if (s < 31) stsA((s + 1) & 1);
        __syncthreads();
    }

    // ---- epilogue via smem for coalesced stores ----
    float* ep = (float*)smem;
#pragma unroll
    for (int mi = 0; mi < 4; mi++) {
        const int r0 = warp_m * 64 + mi * 16 + (lane >> 2);
#pragma unroll
        for (int ni = 0; ni < 4; ni++) {
            const int c = warp_n * 32 + ni * 8 + 2 * (lane & 3);
            const float b0 = bias[n0 + c];
            const float b1 = bias[n0 + c + 1];
            if (MODE == 0) {
                ep[(c    ) * EPS + r0    ] = acc[mi][ni][0] + b0;
                ep[(c + 1) * EPS + r0    ] = acc[mi][ni][1] + b1;
                ep[(c    ) * EPS + r0 + 8] = acc[mi][ni][2] + b0;
                ep[(c + 1) * EPS + r0 + 8] = acc[mi][ni][3] + b1;
            } else {
                ep[(r0    ) * EPS + c    ] = acc[mi][ni][0] + b0;
                ep[(r0    ) * EPS + c + 1] = acc[mi][ni][1] + b1;
                ep[(r0 + 8) * EPS + c    ] = acc[mi][ni][2] + b0;
                ep[(r0 + 8) * EPS + c + 1] = acc[mi][ni][3] + b1;
            }
        }
    }
    __syncthreads();
#pragma unroll
    for (int j = 0; j < 16; j++) {
        const int row = j * 8 + wid;
        const float4 v = *(const float4*)(ep + row * EPS + lane * 4);
        if (MODE == 0)
            *(float4*)(C + ((size_t)(bb * DMODEL + n0 + row)) * LSEQ + l0 + lane * 4) = v;
        else
            *(float4*)(C + (size_t)(m0 + row) * DMODEL + n0 + lane * 4) = v;
    }
}

// ---------------------------------------------------------------------------
// Fused correlation kernel: radix-8 FFT; FFT2 stage0 fused with spectrum pass.
// 64KB smem. Result of FFT2 lands in Az; vbuf aliases Bz.
// ---------------------------------------------------------------------------
#define CORR_SMEM_BYTES (2 * LSEQ * 8 + 64 * 4)

__device__ __forceinline__ void radix8_store(
    float2* dst, const float2* x, int Jm, int k, int m)
{
    const float C707 = 0.70710678118654752f;
    const float2 x0 = x[0], x1 = x[1], x2 = x[2], x3 = x[3];
    const float2 x4 = x[4], x5 = x[5], x6 = x[6], x7 = x[7];
    const float a0x = x0.x + x4.x, a0y = x0.y + x4.y;
    const float a1x = x0.x - x4.x, a1y = x0.y - x4.y;
    const float b0x = x2.x + x6.x, b0y = x2.y + x6.y;
    const float b1x = x2.x - x6.x, b1y = x2.y - x6.y;
    const float E0x = a0x + b0x, E0y = a0y + b0y;
    const float E1x = a1x + b1y, E1y = a1y - b1x;
    const float E2x = a0x - b0x, E2y = a0y - b0y;
    const float E3x = a1x - b1y, E3y = a1y + b1x;
    const float c0x = x1.x + x5.x, c0y = x1.y + x5.y;
    const float c1x = x1.x - x5.x, c1y = x1.y - x5.y;
    const float d0x = x3.x + x7.x, d0y = x3.y + x7.y;
    const float d1x = x3.x - x7.x, d1y = x3.y - x7.y;
    const float O0x = c0x + d0x, O0y = c0y + d0y;
    const float O1x = c1x + d1y, O1y = c1y - d1x;
    const float O2x = c0x - d0x, O2y = c0y - d0y;
    const float O3x = c1x - d1y, O3y = c1y + d1x;
    const float t1x = C707 * (O1x + O1y), t1y = C707 * (O1y - O1x);
    const float t2x = O2y,               t2y = -O2x;
    const float t3x = C707 * (O3y - O3x), t3y = -C707 * (O3x + O3y);
    const float2 y0 = make_float2(E0x + O0x, E0y + O0y);
    const float2 y4 = make_float2(E0x - O0x, E0y - O0y);
    const float2 y1 = make_float2(E1x + t1x, E1y + t1y);
    const float2 y5 = make_float2(E1x - t1x, E1y - t1y);
    const float2 y2 = make_float2(E2x + t2x, E2y + t2y);
    const float2 y6 = make_float2(E2x - t2x, E2y - t2y);
    const float2 y3 = make_float2(E3x + t3x, E3y + t3y);
    const float2 y7 = make_float2(E3x - t3x, E3y - t3y);
    const float ang = -1.5339807878856412e-3f * (float)Jm;
    float s1, cc1;
    __sincosf(ang, &s1, &cc1);
    const float2 w1 = make_float2(cc1, s1);
    const float2 w2 = cmul(w1, w1);
    const float2 w3 = cmul(w2, w1);
    const float2 w4 = cmul(w2, w2);
    const float2 w5 = cmul(w3, w2);
    const float2 w6 = cmul(w3, w3);
    const float2 w7 = cmul(w4, w3);
    const int base = 8 * Jm + k;
    dst[base]         = y0;
    dst[base + m]     = cmul(y1, w1);
    dst[base + 2 * m] = cmul(y2, w2);
    dst[base + 3 * m] = cmul(y3, w3);
    dst[base + 4 * m] = cmul(y4, w4);
    dst[base + 5 * m] = cmul(y5, w5);
    dst[base + 6 * m] = cmul(y6, w6);
    dst[base + 7 * m] = cmul(y7, w7);
}

__device__ __forceinline__ void fft4096(float2* buf0, float2* buf1, int tid)
{
    float2* src = buf0;
    float2* dst = buf1;
    int m = 1;
    for (int st = 0; st < 4; st++) {
        __syncthreads();
        const int k  = tid & (m - 1);
        const int Jm = tid - k;
        float2 x[8];
#pragma unroll
        for (int p = 0; p < 8; p++) x[p] = src[tid + 512 * p];
        radix8_store(dst, x, Jm, k, m);
        float2* t = src; src = dst; dst = t;
        m <<= 3;
    }
    __syncthreads();
}

// spectrum of the packed z-FFT: S(f) = conj(Q(f) * conj(K(f)))
__device__ __forceinline__ float2 spec_at(const float2* Az, int f)
{
    const float2 zf = Az[f];
    const float2 zc = Az[(LSEQ - f) & (LSEQ - 1)];
    const float qx = 0.5f * (zf.x + zc.x);
    const float qy = 0.5f * (zf.y - zc.y);
    const float dx = 0.5f * (zf.x - zc.x);
    const float dy = 0.5f * (zf.y + zc.y);
    const float kx = dy;
    const float ky = -dx;
    return make_float2(qx * kx + qy * ky, -(qy * kx - qx * ky));
}

// FFT of the spectrum, stage0 fused (reads Z from Az on the fly).
// Stage writes: Bz, Az, Bz, Az  -> final result in Az.
__device__ __forceinline__ void fft4096_spec(float2* Az, float2* Bz, int tid)
{
    {
        float2 x[8];
#pragma unroll
        for (int p = 0; p < 8; p++) x[p] = spec_at(Az, tid + 512 * p);
        radix8_store(Bz, x, tid, 0, 1);
    }
    float2* src = Bz;
    float2* dst = Az;
    int m = 8;
    for (int st = 0; st < 3; st++) {
        __syncthreads();
        const int k  = tid & (m - 1);
        const int Jm = tid - k;
        float2 x[8];
#pragma unroll
        for (int p = 0; p < 8; p++) x[p] = src[tid + 512 * p];
        radix8_store(dst, x, Jm, k, m);
        float2* t = src; src = dst; dst = t;
        m <<= 3;
    }
    __syncthreads();
}

__global__ void __launch_bounds__(512, 2) corr_kernel(
    const float* __restrict__ qT, const float* __restrict__ kT,
    const float* __restrict__ vT, __half* __restrict__ aHi)
{
    float* smem = (float*)smem_raw;
    float2* Az   = (float2*)smem;          // FFT2 result lands here
    float2* Bz   = Az + LSEQ;              // reused as vbuf after FFT2
    float*  tail = (float*)(Bz + LSEQ);
    float*  rval = tail;                   // 16
    int*    ridx = (int*)(rval + 16);      // 16
    float*  wts  = (float*)(ridx + 16);    // 16
    int*    dly  = (int*)(wts + 16);       // 16
    float*  vbuf = (float*)Bz;             // alias (valid after FFT2)

    const int tid = threadIdx.x;
    const size_t row = blockIdx.x;
    const float* qp = qT + row * LSEQ;
    const float* kp = kT + row * LSEQ;
    const float* vp = vT + row * LSEQ;

#pragma unroll
    for (int i4 = tid; i4 < LSEQ / 4; i4 += 512) {
        const float4 q4 = ((const float4*)qp)[i4];
        const float4 k4 = ((const float4*)kp)[i4];
        Az[i4 * 4 + 0] = make_float2(q4.x, k4.x);
        Az[i4 * 4 + 1] = make_float2(q4.y, k4.y);
        Az[i4 * 4 + 2] = make_float2(q4.z, k4.z);
        Az[i4 * 4 + 3] = make_float2(q4.w, k4.w);
    }

    fft4096(Az, Bz, tid);        // Z = fft(q + i k), result in Az
    fft4096_spec(Az, Bz, tid);   // corr*N = Re(fft(S)), result in Az

    float cv[8];
#pragma unroll
    for (int c = 0; c < 8; c++) cv[c] = Az[tid + 512 * c].x;

#pragma unroll
    for (int i4 = tid; i4 < LSEQ / 4; i4 += 512)
        *(float4*)(vbuf + i4 * 4) = ((const float4*)vp)[i4];

    const int lane = tid & 31;
    const int wrp  = tid >> 5;
    for (int it = 0; it < TOPK; it++) {
        float best = cv[0];
        int   bc   = 0;
#pragma unroll
        for (int c = 1; c < 8; c++)
            if (cv[c] > best) { best = cv[c]; bc = c; }
        int bi = tid + 512 * bc;
#pragma unroll
        for (int off = 16; off; off >>= 1) {
            const float ov = __shfl_down_sync(0xffffffffu, best, off);
            const int   oi = __shfl_down_sync(0xffffffffu, bi, off);
            if (ov > best || (ov == best && oi < bi)) { best = ov; bi = oi; }
        }
        if (lane == 0) { rval[wrp] = best; ridx[wrp] = bi; }
        __syncthreads();
        if (tid < 32) {
            float v = (lane < 16) ? rval[lane] : -INFINITY;
            int   i = (lane < 16) ? ridx[lane] : LSEQ;
#pragma unroll
            for (int off = 8; off; off >>= 1) {
                const float ov = __shfl_down_sync(0xffffffffu, v, off);
                const int   oi = __shfl_down_sync(0xffffffffu, i, off);
                if (ov > v || (ov == v && oi < i)) { v = ov; i = oi; }
            }
            if (lane == 0) { wts[it] = v * (1.0f / (float)LSEQ); dly[it] = i; }
        }
        __syncthreads();
        const int gi = dly[it];
        if (tid == (gi & 511)) cv[gi >> 9] = -INFINITY;
    }

    if (tid == 0) {
        float mx = wts[0];
        for (int i = 1; i < TOPK; i++) mx = fmaxf(mx, wts[i]);
        float s = 0.0f;
        for (int i = 0; i < TOPK; i++) { const float e = expf(wts[i] - mx); wts[i] = e; s += e; }
        const float inv = 1.0f / s;
        for (int i = 0; i < TOPK; i++) wts[i] *= inv;
    }
    __syncthreads();

    __half* oh = aHi + row * LSEQ;
    for (int t = tid; t < LSEQ; t += 512) {
        float acc = 0.0f;
#pragma unroll
        for (int i = 0; i < TOPK; i++)
            acc += wts[i] * vbuf[(t + dly[i]) & (LSEQ - 1)];
        oh[t] = __float2half_rn(acc);
    }
}

// ---------------------------------------------------------------------------
// Launch
// ---------------------------------------------------------------------------
extern "C" void kernel_launch(void* const* d_in, const int* in_sizes, int n_in,
                              void* d_out, int out_size)
{
    const float* q  = (const float*)d_in[0];
    const float* k  = (const float*)d_in[1];
    const float* v  = (const float*)d_in[2];
    const float* Wq = (const float*)d_in[3];
    const float* bq = (const float*)d_in[4];
    const float* Wk = (const float*)d_in[5];
    const float* bk = (const float*)d_in[6];
    const float* Wv = (const float*)d_in[7];
    const float* bv = (const float*)d_in[8];
    const float* Wo = (const float*)d_in[9];
    const float* bo = (const float*)d_in[10];
    float* out = (float*)d_out;

    float  *qT, *kT, *vT;
    __half *ahi, *wthi, *wtlo;
    cudaGetSymbolAddress((void**)&qT,   g_qT);
    cudaGetSymbolAddress((void**)&kT,   g_kT);
    cudaGetSymbolAddress((void**)&vT,   g_vT);
    cudaGetSymbolAddress((void**)&ahi,  g_a_hi);
    cudaGetSymbolAddress((void**)&wthi, g_wt_hi);
    cudaGetSymbolAddress((void**)&wtlo, g_wt_lo);

    cudaFuncSetAttribute(hgemm_kernel<0,3>, cudaFuncAttributeMaxDynamicSharedMemorySize, GEMM_SMEM);
    cudaFuncSetAttribute(hgemm_kernel<0,1>, cudaFuncAttributeMaxDynamicSharedMemorySize, GEMM_SMEM);
    cudaFuncSetAttribute(hgemm_kernel<1,1>, cudaFuncAttributeMaxDynamicSharedMemorySize, GEMM_SMEM);
    cudaFuncSetAttribute(corr_kernel,       cudaFuncAttributeMaxDynamicSharedMemorySize, CORR_SMEM_BYTES);

    const int WSZ = DMODEL * DMODEL;
    wsplit_kernel<<<dim3(32, 32, 4), 256>>>(Wq, Wk, Wv, Wo, wthi, wtlo);

    const dim3 gg(DMODEL / 128, MTOT / 128);   // (8, 256)

    hgemm_kernel<0,3><<<gg, 256, GEMM_SMEM>>>(q, wthi + 0 * WSZ, wtlo + 0 * WSZ, bq, qT);
    hgemm_kernel<0,3><<<gg, 256, GEMM_SMEM>>>(k, wthi + 1 * WSZ, wtlo + 1 * WSZ, bk, kT);
    hgemm_kernel<0,1><<<gg, 256, GEMM_SMEM>>>(v, wthi + 2 * WSZ, wtlo + 2 * WSZ, bv, vT);

    corr_kernel<<<NROWS, 512, CORR_SMEM_BYTES>>>(qT, kT, vT, ahi);

    hgemm_kernel<1,1><<<gg, 256, GEMM_SMEM>>>(ahi, wthi + 3 * WSZ, wtlo + 3 * WSZ, bo, out);
}